// round 16
// baseline (speedup 1.0000x reference)
#include <cuda_runtime.h>
#include <cuda_bf16.h>
#include <cstdint>

// N = 400 nodes, E = N*(N-1) = 159600 edges, B = 32 batch.
// Output [B, E, 2] f32: out[b,e,:] = adj[i,j]!=0 ? (0,1) : (1,0),
// edge e -> (i = e/399, j = r + (r>=i)), r = e%399  (np.where(~eye) order).
//
// CONVERGED AT HW ROOFLINE: 10 structural variants (STG.128/.256, plain/.cs,
// bulk-only, dual splits 12/20 & 16/16 & 20/12, occupancy 10-72%, grids
// 148-1248, balanced/unbalanced chunks) all pin at ~2400 B/cyc chip-wide
// store throughput -> 9.5-9.9us kernel for the irreducible 40.85MB output.
// Controlled experiments falsified: path concurrency (R11), SM balance (R7),
// wavefront alignment / store width (R8), cache-op policy (R13). The limiter
// is a shared downstream L2 write port (~3/8 of the 6300 B/cyc read cap).
//
// This is the best-measured-total config (10.72us): 150 CTAs x 256 threads,
// batches 0-11 via streaming STG.128, batches 12-31 via per-thread
// cp.async.bulk broadcasts of a once-computed smem tile.

#define N_NODES 400
#define N_M1    399
#define E_PAIRS 79800           // float4 elements per batch
#define BATCH   32
#define TILE_F4 532
#define N_TILES 150             // 150 * 532 = 79800
#define TILE_BYTES (TILE_F4 * 16)   // 8512
#define NB_STG  12              // batches via STG
#define NB_BULK (BATCH - NB_STG)    // 20 batches via cp.async.bulk

__device__ __forceinline__ float4 pair_val(const float* __restrict__ adj, int p)
{
    const int e0 = 2 * p;
    const int e1 = e0 + 1;
    int i0 = e0 / N_M1;
    int r0 = e0 - i0 * N_M1;
    int j0 = r0 + (r0 >= i0 ? 1 : 0);
    int i1 = e1 / N_M1;
    int r1 = e1 - i1 * N_M1;
    int j1 = r1 + (r1 >= i1 ? 1 : 0);
    const float t0 = (__ldg(&adj[i0 * N_NODES + j0]) != 0.0f) ? 1.0f : 0.0f;
    const float t1 = (__ldg(&adj[i1 * N_NODES + j1]) != 0.0f) ? 1.0f : 0.0f;
    return make_float4(1.0f - t0, t0, 1.0f - t1, t1);
}

__global__ __launch_bounds__(256)
void edge_onehot_dual_kernel(const float* __restrict__ adj, float4* __restrict__ out)
{
    __shared__ alignas(128) float4 buf[TILE_F4];

    const int tid = threadIdx.x;
    const int base_p = blockIdx.x * TILE_F4;

    // ---- Phase 1: compute tile once; keep values in regs AND mirror to smem.
    float4 v0, v1, v2;
    {
        v0 = pair_val(adj, base_p + tid);           // slot 0: [0,256)
        buf[tid] = v0;
    }
    {
        v1 = pair_val(adj, base_p + tid + 256);     // slot 1: [256,512)
        buf[tid + 256] = v1;
    }
    const bool has2 = (tid < TILE_F4 - 512);        // 20 threads: [512,532)
    if (has2) {
        v2 = pair_val(adj, base_p + tid + 512);
        buf[tid + 512] = v2;
    }

    __syncthreads();

    // ---- Phase 2a: async-engine path. Threads 0..NB_BULK-1 each broadcast
    // the smem tile to one batch image with their own bulk group.
    if (tid < NB_BULK) {
        asm volatile("fence.proxy.async.shared::cta;" ::: "memory");
        uint32_t smem_addr;
        asm("{ .reg .u64 t; cvta.to.shared.u64 t, %1; cvt.u32.u64 %0, t; }"
            : "=r"(smem_addr) : "l"(buf));
        const int b = NB_STG + tid;
        float4* dst = out + (size_t)b * E_PAIRS + base_p;
        asm volatile(
            "cp.async.bulk.global.shared::cta.bulk_group [%0], [%1], %2;"
            :: "l"(dst), "r"(smem_addr), "r"((uint32_t)TILE_BYTES)
            : "memory");
        asm volatile("cp.async.bulk.commit_group;" ::: "memory");
    }

    // ---- Phase 2b: LSU path. All threads store register values to
    // batches [0, NB_STG) with streaming STG.128.
    float4* base0 = out + base_p + tid;
#pragma unroll
    for (int b = 0; b < NB_STG; ++b) {
        float4* d = base0 + (size_t)b * E_PAIRS;
        __stcs(d, v0);
        __stcs(d + 256, v1);
        if (has2) __stcs(d + 512, v2);
    }

    // ---- Drain bulk copies before CTA exit (smem lifetime).
    if (tid < NB_BULK) {
        asm volatile("cp.async.bulk.wait_group 0;" ::: "memory");
    }
    __syncthreads();
}

extern "C" void kernel_launch(void* const* d_in, const int* in_sizes, int n_in,
                              void* d_out, int out_size)
{
    // metadata order: inputs, weather, rel_rec, rel_send, adj_matrix
    const float* adj = (const float*)d_in[4];
    float4* out = (float4*)d_out;

    edge_onehot_dual_kernel<<<N_TILES, 256>>>(adj, out);
}